// round 2
// baseline (speedup 1.0000x reference)
#include <cuda_runtime.h>
#include <stdint.h>

// ---------------------------------------------------------------------------
// ExpertBuffer fetch_on_demand, fully fused single kernel.
// out = concat(w13_cache', w13_bias_cache', w2_cache', w2_bias_cache')
// where cache'[s] = src[e] if slot s was scattered (last pair wins) else cache[s].
//
// All addressing in 32-bit unsigned float4 units (total ~12.6M < 2^32).
// Per-expert sizes are powers of two for this problem -> shift-based slot math,
// with a division fallback if a future shape isn't pow2.
// ---------------------------------------------------------------------------

#define MAX_SLOTS 1024

struct Region {
    const float4* src;
    const float4* cache;
    unsigned base;   // prefix offset of this region in out (float4 units)
    unsigned per4;   // float4s per expert/slot in this region
    int shift;       // log2(per4) if pow2, else -1
};

__device__ __forceinline__ float4 fetch_one(
    unsigned i,
    const Region& r0, const Region& r1, const Region& r2, const Region& r3,
    unsigned off1, unsigned off2, unsigned off3,
    const int* __restrict__ smap)
{
    const Region* r;
    if (i < off1)      r = &r0;
    else if (i < off2) r = &r1;
    else if (i < off3) r = &r2;
    else               r = &r3;

    unsigned local = i - r->base;
    unsigned s, off;
    if (r->shift >= 0) {
        s   = local >> r->shift;
        off = local & (r->per4 - 1u);
    } else {
        s   = local / r->per4;
        off = local - s * r->per4;
    }
    int e = smap[s];
    const float4* p = (e >= 0) ? (r->src + (size_t)(unsigned)e * r->per4)
                               : (r->cache + (size_t)s * r->per4);
    return p[off];
}

__global__ void __launch_bounds__(256)
fused_gather_copy(
    const float4* __restrict__ w13_src,  const float4* __restrict__ w13_cache,
    const float4* __restrict__ b13_src,  const float4* __restrict__ b13_cache,
    const float4* __restrict__ w2_src,   const float4* __restrict__ w2_cache,
    const float4* __restrict__ b2_src,   const float4* __restrict__ b2_cache,
    float4* __restrict__ out,
    const int* __restrict__ expert_ids, const int* __restrict__ slot_ids,
    int n_pairs, int n_slots,
    unsigned off1, unsigned off2, unsigned off3, unsigned total,
    unsigned per13, int sh13, unsigned perb13, int shb13,
    unsigned per2,  int sh2,  unsigned perb2,  int shb2)
{
    __shared__ int smap[MAX_SLOTS];

    // Resolve slot -> expert map per block. Tiny index arrays; last pair wins.
    for (int s = threadIdx.x; s < n_slots; s += blockDim.x) {
        int e = -1;
        for (int i = 0; i < n_pairs; ++i)
            if (slot_ids[i] == s) e = expert_ids[i];
        smap[s] = e;
    }
    __syncthreads();

    Region r0 = { w13_src, w13_cache, 0u,   per13,  sh13  };
    Region r1 = { b13_src, b13_cache, off1, perb13, shb13 };
    Region r2 = { w2_src,  w2_cache,  off2, per2,   sh2   };
    Region r3 = { b2_src,  b2_cache,  off3, perb2,  shb2  };

    unsigned stride = blockDim.x * gridDim.x;
    unsigned i = blockIdx.x * blockDim.x + threadIdx.x;

    // 4-way unrolled grid-stride: 4 independent LDG.128 in flight per iter.
    for (; i + 3u * stride < total; i += 4u * stride) {
        float4 v0 = fetch_one(i,              r0, r1, r2, r3, off1, off2, off3, smap);
        float4 v1 = fetch_one(i +      stride, r0, r1, r2, r3, off1, off2, off3, smap);
        float4 v2 = fetch_one(i + 2u * stride, r0, r1, r2, r3, off1, off2, off3, smap);
        float4 v3 = fetch_one(i + 3u * stride, r0, r1, r2, r3, off1, off2, off3, smap);
        out[i]               = v0;
        out[i +      stride] = v1;
        out[i + 2u * stride] = v2;
        out[i + 3u * stride] = v3;
    }
    for (; i < total; i += stride)
        out[i] = fetch_one(i, r0, r1, r2, r3, off1, off2, off3, smap);
}

static inline int ilog2_if_pow2(long v) {
    if (v > 0 && (v & (v - 1)) == 0) {
        int s = 0;
        while ((1L << s) < v) ++s;
        return s;
    }
    return -1;
}

extern "C" void kernel_launch(void* const* d_in, const int* in_sizes, int n_in,
                              void* d_out, int out_size) {
    const float* w13_src    = (const float*)d_in[0];
    const float* b13_src    = (const float*)d_in[1];
    const float* w2_src     = (const float*)d_in[2];
    const float* b2_src     = (const float*)d_in[3];
    const float* w13_cache  = (const float*)d_in[4];
    const float* b13_cache  = (const float*)d_in[5];
    const float* w2_cache   = (const float*)d_in[6];
    const float* b2_cache   = (const float*)d_in[7];
    const int*   expert_ids = (const int*)d_in[8];
    const int*   slot_ids   = (const int*)d_in[9];

    int n_pairs = in_sizes[8];
    int n_slots = in_sizes[9];

    long n13  = in_sizes[4];
    long nb13 = in_sizes[5];
    long n2   = in_sizes[6];
    long nb2  = in_sizes[7];

    unsigned per13  = (unsigned)((n13  / n_slots) >> 2);   // float4 per slot
    unsigned perb13 = (unsigned)((nb13 / n_slots) >> 2);
    unsigned per2   = (unsigned)((n2   / n_slots) >> 2);
    unsigned perb2  = (unsigned)((nb2  / n_slots) >> 2);

    unsigned off1 = (unsigned)(n13 >> 2);
    unsigned off2 = off1 + (unsigned)(nb13 >> 2);
    unsigned off3 = off2 + (unsigned)(n2 >> 2);
    unsigned total = off3 + (unsigned)(nb2 >> 2);

    int sh13  = ilog2_if_pow2(per13);
    int shb13 = ilog2_if_pow2(perb13);
    int sh2   = ilog2_if_pow2(per2);
    int shb2  = ilog2_if_pow2(perb2);

    // ~16 blocks per SM worth of threads; each thread moves ~20 float4s.
    int threads = 256;
    int blocks  = 148 * 16;
    unsigned max_blocks = (total + threads - 1) / threads;
    if ((unsigned)blocks > max_blocks) blocks = (int)max_blocks;

    fused_gather_copy<<<blocks, threads>>>(
        (const float4*)w13_src, (const float4*)w13_cache,
        (const float4*)b13_src, (const float4*)b13_cache,
        (const float4*)w2_src,  (const float4*)w2_cache,
        (const float4*)b2_src,  (const float4*)b2_cache,
        (float4*)d_out,
        expert_ids, slot_ids, n_pairs, n_slots,
        off1, off2, off3, total,
        per13, sh13, perb13, shb13,
        per2, sh2, perb2, shb2);
}

// round 3
// speedup vs baseline: 1.0875x; 1.0875x over previous
#include <cuda_runtime.h>
#include <stdint.h>

// ---------------------------------------------------------------------------
// ExpertBuffer fetch_on_demand, fused single kernel, streaming ld/st.
// out = concat(w13_cache', w13_bias_cache', w2_cache', w2_bias_cache')
// where cache'[s] = src[e] if slot s was scattered (last pair wins) else cache[s].
// ---------------------------------------------------------------------------

#define MAX_SLOTS 1024
#define UNROLL 8

struct Region {
    const float4* src;
    const float4* cache;
    unsigned base;   // prefix offset of this region in out (float4 units)
    unsigned per4;   // float4s per expert/slot in this region
    int shift;       // log2(per4) if pow2, else -1
};

__device__ __forceinline__ float4 fetch_one(
    unsigned i,
    const Region& r0, const Region& r1, const Region& r2, const Region& r3,
    unsigned off1, unsigned off2, unsigned off3,
    const int* __restrict__ smap)
{
    const Region* r;
    if (i < off1)      r = &r0;
    else if (i < off2) r = &r1;
    else if (i < off3) r = &r2;
    else               r = &r3;

    unsigned local = i - r->base;
    unsigned s, off;
    if (r->shift >= 0) {
        s   = local >> r->shift;
        off = local & (r->per4 - 1u);
    } else {
        s   = local / r->per4;
        off = local - s * r->per4;
    }
    int e = smap[s];
    const float4* p = (e >= 0) ? (r->src + (size_t)(unsigned)e * r->per4)
                               : (r->cache + (size_t)s * r->per4);
    return __ldcs(p + off);   // streaming load: no reuse, evict-first
}

__global__ void __launch_bounds__(256)
fused_gather_copy(
    const float4* __restrict__ w13_src,  const float4* __restrict__ w13_cache,
    const float4* __restrict__ b13_src,  const float4* __restrict__ b13_cache,
    const float4* __restrict__ w2_src,   const float4* __restrict__ w2_cache,
    const float4* __restrict__ b2_src,   const float4* __restrict__ b2_cache,
    float4* __restrict__ out,
    const int* __restrict__ expert_ids, const int* __restrict__ slot_ids,
    int n_pairs, int n_slots,
    unsigned off1, unsigned off2, unsigned off3, unsigned total,
    unsigned per13, int sh13, unsigned perb13, int shb13,
    unsigned per2,  int sh2,  unsigned perb2,  int shb2)
{
    __shared__ int smap[MAX_SLOTS];

    // Resolve slot -> expert map per block (index arrays are tiny, L2-hot).
    for (int s = threadIdx.x; s < n_slots; s += blockDim.x) {
        int e = -1;
        for (int i = 0; i < n_pairs; ++i)
            if (slot_ids[i] == s) e = expert_ids[i];
        smap[s] = e;
    }
    __syncthreads();

    Region r0 = { w13_src, w13_cache, 0u,   per13,  sh13  };
    Region r1 = { b13_src, b13_cache, off1, perb13, shb13 };
    Region r2 = { w2_src,  w2_cache,  off2, per2,   sh2   };
    Region r3 = { b2_src,  b2_cache,  off3, perb2,  shb2  };

    const unsigned stride = blockDim.x * gridDim.x;
    unsigned i = blockIdx.x * blockDim.x + threadIdx.x;

    // UNROLL independent LDG.128 in flight before the store burst.
    for (; i + (UNROLL - 1u) * stride < total; i += (unsigned)UNROLL * stride) {
        float4 v[UNROLL];
        #pragma unroll
        for (int u = 0; u < UNROLL; ++u)
            v[u] = fetch_one(i + (unsigned)u * stride,
                             r0, r1, r2, r3, off1, off2, off3, smap);
        #pragma unroll
        for (int u = 0; u < UNROLL; ++u)
            __stcs(out + i + (unsigned)u * stride, v[u]);  // streaming store
    }
    for (; i < total; i += stride)
        __stcs(out + i, fetch_one(i, r0, r1, r2, r3, off1, off2, off3, smap));
}

static inline int ilog2_if_pow2(long v) {
    if (v > 0 && (v & (v - 1)) == 0) {
        int s = 0;
        while ((1L << s) < v) ++s;
        return s;
    }
    return -1;
}

extern "C" void kernel_launch(void* const* d_in, const int* in_sizes, int n_in,
                              void* d_out, int out_size) {
    const float* w13_src    = (const float*)d_in[0];
    const float* b13_src    = (const float*)d_in[1];
    const float* w2_src     = (const float*)d_in[2];
    const float* b2_src     = (const float*)d_in[3];
    const float* w13_cache  = (const float*)d_in[4];
    const float* b13_cache  = (const float*)d_in[5];
    const float* w2_cache   = (const float*)d_in[6];
    const float* b2_cache   = (const float*)d_in[7];
    const int*   expert_ids = (const int*)d_in[8];
    const int*   slot_ids   = (const int*)d_in[9];

    int n_pairs = in_sizes[8];
    int n_slots = in_sizes[9];

    long n13  = in_sizes[4];
    long nb13 = in_sizes[5];
    long n2   = in_sizes[6];
    long nb2  = in_sizes[7];

    unsigned per13  = (unsigned)((n13  / n_slots) >> 2);   // float4 per slot
    unsigned perb13 = (unsigned)((nb13 / n_slots) >> 2);
    unsigned per2   = (unsigned)((n2   / n_slots) >> 2);
    unsigned perb2  = (unsigned)((nb2  / n_slots) >> 2);

    unsigned off1 = (unsigned)(n13 >> 2);
    unsigned off2 = off1 + (unsigned)(nb13 >> 2);
    unsigned off3 = off2 + (unsigned)(n2 >> 2);
    unsigned total = off3 + (unsigned)(nb2 >> 2);

    int sh13  = ilog2_if_pow2(per13);
    int shb13 = ilog2_if_pow2(perb13);
    int sh2   = ilog2_if_pow2(per2);
    int shb2  = ilog2_if_pow2(perb2);

    // Exactly one resident wave: 8 blocks/SM * 256 threads = 2048 threads/SM.
    int threads = 256;
    int blocks  = 148 * 8;
    unsigned max_blocks = (total + threads - 1) / threads;
    if ((unsigned)blocks > max_blocks) blocks = (int)max_blocks;

    fused_gather_copy<<<blocks, threads>>>(
        (const float4*)w13_src, (const float4*)w13_cache,
        (const float4*)b13_src, (const float4*)b13_cache,
        (const float4*)w2_src,  (const float4*)w2_cache,
        (const float4*)b2_src,  (const float4*)b2_cache,
        (float4*)d_out,
        expert_ids, slot_ids, n_pairs, n_slots,
        off1, off2, off3, total,
        per13, sh13, perb13, shb13,
        per2, sh2, perb2, shb2);
}